// round 16
// baseline (speedup 1.0000x reference)
#include <cuda_runtime.h>
#include <cuda_bf16.h>

// Warp-autonomous, TWO-threads-per-row hierarchical softmax.
// Split at leaf 30 (no sibling group crosses it): role A = leaves 0..29
// (groups 0,1), role B = leaves 30..64 (groups 2..7). 4 shfl.xor(16) exchange
// the cross-half scalars. One warp per block, 16 rows/warp, 4864B smem ->
// ~23 resident warps/SM (reg-bound), same total instruction stream as before.
// Fused output layout (flat): [ leaf_path_probs (N*65) | node_probs (N*76) ]

#define NT      32
#define ROWS_W  16
#define WREG    (ROWS_W * 76)   // 1216 floats per warp region

__global__ __launch_bounds__(NT)
void molemap_kernel(const float* __restrict__ x,
                    float* __restrict__ out_path,
                    float* __restrict__ out_node)
{
    __shared__ __align__(16) float wbuf[WREG];   // 4864 B: input -> path -> node

    const int lane = threadIdx.x;                // one warp per block
    const long long wrow0 = (long long)blockIdx.x * ROWS_W;

    // ---- Phase A: warp-coalesced load 16 rows: 1040 floats = 260 float4 ----
    {
        const float4* in4 = reinterpret_cast<const float4*>(x + wrow0 * 65);
        float4* b4 = reinterpret_cast<float4*>(wbuf);
        #pragma unroll
        for (int k = 0; k < 9; ++k) {
            int idx = lane + k * 32;
            if (idx < 260) b4[idx] = in4[idx];
        }
    }
    __syncwarp();

    // ---- Phase B: pair-per-row compute ----
    const int r    = lane & 15;    // row within warp
    const int role = lane >> 4;    // 0: leaves 0..29 | 1: leaves 30..64
    float* rx = wbuf + r * 65;

    float v[35];                   // A uses [0..29], B uses [0..34]
    float gr[6];                   // A: grcp of G0,G1 | B: grcp of G2..G7
    float pl2[8], pt0 = 0.f, pt1 = 0.f;   // meaningful in B lanes
    float mA0 = 0.f, mA1 = 0.f;    // A: mean0, mean1

#define GSTAT(VA, VB, GI, RSZ)                                          \
    {                                                                   \
        float mm = v[VA], s = 0.f;                                      \
        _Pragma("unroll")                                               \
        for (int i = VA; i < VB; ++i) { s += v[i]; mm = fmaxf(mm, v[i]); } \
        float e = 0.f;                                                  \
        _Pragma("unroll")                                               \
        for (int i = VA; i < VB; ++i) { v[i] = __expf(v[i] - mm); e += v[i]; } \
        gr[GI] = 1.0f / e; msc[GI] = s * (RSZ);                         \
    }

    float msc[6];                  // group means (A: [0..1]=mean0,1 | B: [0..5]=mean2..7)
    if (role == 0) {
        #pragma unroll
        for (int i = 0; i < 30; ++i) v[i] = rx[i];
        GSTAT(0,  7, 0, 1.0f/7.0f)     // G0
        GSTAT(7, 30, 1, 1.0f/23.0f)    // G1
        mA0 = msc[0]; mA1 = msc[1];
    } else {
        const float* rb = rx + 30;
        #pragma unroll
        for (int i = 0; i < 35; ++i) v[i] = rb[i];
        GSTAT( 0, 18, 0, 1.0f/18.0f)   // G2 (leaves 30..47)
        GSTAT(18, 23, 1, 1.0f/5.0f)    // G3 (48..52)
        GSTAT(23, 28, 2, 1.0f/5.0f)    // G4 (53..57)
        GSTAT(28, 29, 3, 1.0f)         // G5 (58)
        GSTAT(29, 32, 4, 1.0f/3.0f)    // G6 (59..61)
        GSTAT(32, 35, 5, 1.0f/3.0f)    // G7 (62..64)
    }
#undef GSTAT

    // exchange A -> B: mean0, mean1 (all lanes participate, converged)
    float xm0 = __shfl_xor_sync(0xffffffffu, mA0, 16);
    float xm1 = __shfl_xor_sync(0xffffffffu, mA1, 16);

    // B computes the hierarchy
    float u0 = 0.f, u1 = 0.f;      // ks for G0, G1 (to send back to A)
    if (role == 1) {
        float m0 = xm0, m1 = xm1;
        float m2 = msc[0], m3 = msc[1], m4 = msc[2], m5 = msc[3], m6 = msc[4], m7 = msc[5];

        float mx0 = fmaxf(fmaxf(m0, m1), fmaxf(m2, m3));
        float e0 = __expf(m0-mx0), e1 = __expf(m1-mx0), e2 = __expf(m2-mx0), e3 = __expf(m3-mx0);
        float r0 = 1.0f / (e0 + e1 + e2 + e3);
        pl2[0] = e0*r0; pl2[1] = e1*r0; pl2[2] = e2*r0; pl2[3] = e3*r0;

        float mx1 = fmaxf(fmaxf(m4, m5), fmaxf(m6, m7));
        float f0 = __expf(m4-mx1), f1 = __expf(m5-mx1), f2 = __expf(m6-mx1), f3 = __expf(m7-mx1);
        float r1 = 1.0f / (f0 + f1 + f2 + f3);
        pl2[4] = f0*r1; pl2[5] = f1*r1; pl2[6] = f2*r1; pl2[7] = f3*r1;

        float t0m = (m0*7.f + m1*23.f + m2*18.f + m3*5.f) * (1.0f/53.0f);
        float t1m = (m4*5.f + m5*1.f + m6*3.f + m7*3.f) * (1.0f/12.0f);
        float mxt = fmaxf(t0m, t1m);
        float t0 = __expf(t0m - mxt), t1 = __expf(t1m - mxt);
        float rt = 1.0f / (t0 + t1);
        pt0 = t0 * rt; pt1 = t1 * rt;

        u0 = pl2[0] * pt0;
        u1 = pl2[1] * pt0;
    }

    // exchange B -> A: path scales for G0, G1
    float ksA0 = __shfl_xor_sync(0xffffffffu, u0, 16);
    float ksA1 = __shfl_xor_sync(0xffffffffu, u1, 16);

    // finalize: v -> leaf probs (kept in regs); path probs -> rx in place
    if (role == 0) {
#define FINA(A, B, GI, KS)                                  \
        _Pragma("unroll")                                   \
        for (int i = A; i < B; ++i) { v[i] *= gr[GI]; rx[i] = v[i] * (KS); }
        FINA(0,  7, 0, ksA0)
        FINA(7, 30, 1, ksA1)
#undef FINA
    } else {
        float* rb = rx + 30;
        float k2 = pl2[2]*pt0, k3 = pl2[3]*pt0, k4 = pl2[4]*pt1,
              k5 = pl2[5]*pt1, k6 = pl2[6]*pt1, k7 = pl2[7]*pt1;
#define FINB(A, B, GI, KS)                                  \
        _Pragma("unroll")                                   \
        for (int i = A; i < B; ++i) { v[i] *= gr[GI]; rb[i] = v[i] * (KS); }
        FINB( 0, 18, 0, k2)
        FINB(18, 23, 1, k3)
        FINB(23, 28, 2, k4)
        FINB(28, 29, 3, k5)
        FINB(29, 32, 4, k6)
        FINB(32, 35, 5, k7)
#undef FINB
    }
    __syncwarp();

    // ---- Phase C: warp-coalesced stream of path probs: 260 float4 ----
    {
        float4* op4 = reinterpret_cast<float4*>(out_path + wrow0 * 65);
        const float4* b4 = reinterpret_cast<const float4*>(wbuf);
        #pragma unroll
        for (int k = 0; k < 9; ++k) {
            int idx = lane + k * 32;
            if (idx < 260) op4[idx] = b4[idx];
        }
    }
    __syncwarp();   // path reads done before node overwrite

    // ---- Phase D: write node rows [16][76] from live registers ----
    {
        float* rn = wbuf + r * 76;
        if (role == 0) {
            #pragma unroll
            for (int i = 0; i < 30; ++i) rn[i] = v[i];
        } else {
            #pragma unroll
            for (int i = 0; i < 35; ++i) rn[30 + i] = v[i];
            #pragma unroll
            for (int g = 0; g < 8; ++g) rn[65 + g] = pl2[g];
            rn[73] = pt0;
            rn[74] = pt1;
            rn[75] = 1.0f;
        }
    }
    __syncwarp();

    // ---- Phase E: warp-coalesced stream of node rows: 1216 floats = 304 float4 ----
    {
        float4* on4 = reinterpret_cast<float4*>(out_node + wrow0 * 76);
        const float4* b4 = reinterpret_cast<const float4*>(wbuf);
        #pragma unroll
        for (int k = 0; k < 10; ++k) {
            int idx = lane + k * 32;
            if (idx < 304) on4[idx] = b4[idx];
        }
    }
}

extern "C" void kernel_launch(void* const* d_in, const int* in_sizes, int n_in,
                              void* d_out, int out_size)
{
    const float* x = (const float*)d_in[0];
    const long long N = (long long)in_sizes[0] / 65;   // 524288
    float* out_path = (float*)d_out;
    float* out_node = out_path + N * 65;

    const int blocks = (int)(N / ROWS_W);              // 32768
    molemap_kernel<<<blocks, NT>>>(x, out_path, out_node);
}

// round 17
// speedup vs baseline: 1.1455x; 1.1455x over previous
#include <cuda_runtime.h>
#include <cuda_bf16.h>
#include <cuda_pipeline.h>

// Warp-autonomous thread-per-row hierarchical softmax with cp.async ping-pong.
// Grid-stride loop over 32-row chunks; each warp prefetches chunk i+1 into its
// alternate smem region (LDGSTS, no register staging) while computing chunk i,
// so every warp keeps a DRAM load in flight ~continuously.
// Fused output layout (flat): [ leaf_path_probs (N*65) | node_probs (N*76) ]

#define NT      64
#define WARPS   2
#define ROWS_W  32
#define WREG    (ROWS_W * 76)   // 2432 floats per region (input 2080 used, node 2432)

__device__ __forceinline__ void prefetch_chunk(const float* __restrict__ x,
                                               long long chunk, float* region, int lane)
{
    const float4* src = reinterpret_cast<const float4*>(x + chunk * (ROWS_W * 65));
    float4* dst = reinterpret_cast<float4*>(region);
    #pragma unroll
    for (int k = 0; k < 17; ++k) {
        int idx = lane + k * 32;
        if (idx < 520) __pipeline_memcpy_async(&dst[idx], &src[idx], 16);
    }
}

__global__ __launch_bounds__(NT)
void molemap_kernel(const float* __restrict__ x,
                    float* __restrict__ out_path,
                    float* __restrict__ out_node,
                    int nChunks, int nWarpsTotal)
{
    __shared__ __align__(16) float buf[WARPS][2][WREG];   // 38912 B/block

    const int w    = threadIdx.x >> 5;
    const int lane = threadIdx.x & 31;
    const int wid  = blockIdx.x * WARPS + w;

    int cur = 0;
    long long c = wid;
    if (c < nChunks) prefetch_chunk(x, c, buf[w][0], lane);
    __pipeline_commit();

    for (; c < nChunks; c += nWarpsTotal) {
        // prefetch next chunk into the other region, then wait for current
        long long cn = c + nWarpsTotal;
        if (cn < nChunks) {
            prefetch_chunk(x, cn, buf[w][cur ^ 1], lane);
            __pipeline_commit();
            __pipeline_wait_prior(1);
        } else {
            __pipeline_wait_prior(0);
        }
        __syncwarp();

        float* wbuf = buf[w][cur];
        const long long wrow0 = c * ROWS_W;

        // ---- compute: thread-per-row; path probs written in place ----
        float v[65];
        float pl2[8], pt0, pt1;
        {
            float* rx = wbuf + lane * 65;   // stride 65 ≡ 1 (mod 32): conflict-free
            #pragma unroll
            for (int i = 0; i < 65; ++i) v[i] = rx[i];

            float grcp[8], mean[8];
#define GROUP_STATS(G, A, B, RSZ)                                       \
            {                                                           \
                float mm = v[A], s = 0.f;                               \
                _Pragma("unroll")                                       \
                for (int i = A; i < B; ++i) { s += v[i]; mm = fmaxf(mm, v[i]); } \
                float e = 0.f;                                          \
                _Pragma("unroll")                                       \
                for (int i = A; i < B; ++i) { v[i] = __expf(v[i] - mm); e += v[i]; } \
                grcp[G] = 1.0f / e; mean[G] = s * (RSZ);                \
            }
            GROUP_STATS(0,  0,  7, 1.0f/7.0f)
            GROUP_STATS(1,  7, 30, 1.0f/23.0f)
            GROUP_STATS(2, 30, 48, 1.0f/18.0f)
            GROUP_STATS(3, 48, 53, 1.0f/5.0f)
            GROUP_STATS(4, 53, 58, 1.0f/5.0f)
            GROUP_STATS(5, 58, 59, 1.0f)
            GROUP_STATS(6, 59, 62, 1.0f/3.0f)
            GROUP_STATS(7, 62, 65, 1.0f/3.0f)
#undef GROUP_STATS

            {
                float mx0 = fmaxf(fmaxf(mean[0], mean[1]), fmaxf(mean[2], mean[3]));
                float e0 = __expf(mean[0]-mx0), e1 = __expf(mean[1]-mx0);
                float e2 = __expf(mean[2]-mx0), e3 = __expf(mean[3]-mx0);
                float r0 = 1.0f / (e0 + e1 + e2 + e3);
                pl2[0] = e0*r0; pl2[1] = e1*r0; pl2[2] = e2*r0; pl2[3] = e3*r0;

                float mx1 = fmaxf(fmaxf(mean[4], mean[5]), fmaxf(mean[6], mean[7]));
                float f0 = __expf(mean[4]-mx1), f1 = __expf(mean[5]-mx1);
                float f2 = __expf(mean[6]-mx1), f3 = __expf(mean[7]-mx1);
                float r1 = 1.0f / (f0 + f1 + f2 + f3);
                pl2[4] = f0*r1; pl2[5] = f1*r1; pl2[6] = f2*r1; pl2[7] = f3*r1;

                float m0 = (mean[0]*7.f + mean[1]*23.f + mean[2]*18.f + mean[3]*5.f) * (1.0f/53.0f);
                float m1 = (mean[4]*5.f + mean[5]*1.f + mean[6]*3.f + mean[7]*3.f) * (1.0f/12.0f);
                float mxt = fmaxf(m0, m1);
                float t0 = __expf(m0 - mxt), t1 = __expf(m1 - mxt);
                float rt = 1.0f / (t0 + t1);
                pt0 = t0 * rt; pt1 = t1 * rt;
            }

            float ks[8];
            #pragma unroll
            for (int g = 0; g < 8; ++g) ks[g] = pl2[g] * (g < 4 ? pt0 : pt1);

#define FINALIZE(G, A, B)                                       \
            {                                                   \
                float rc = grcp[G], kk = ks[G];                 \
                _Pragma("unroll")                               \
                for (int i = A; i < B; ++i) {                   \
                    v[i] *= rc;            /* leaf prob */      \
                    rx[i] = v[i] * kk;     /* path prob */      \
                }                                               \
            }
            FINALIZE(0,  0,  7)  FINALIZE(1,  7, 30)
            FINALIZE(2, 30, 48)  FINALIZE(3, 48, 53)
            FINALIZE(4, 53, 58)  FINALIZE(5, 58, 59)
            FINALIZE(6, 59, 62)  FINALIZE(7, 62, 65)
#undef FINALIZE
        }
        __syncwarp();

        // ---- stream path probs: 520 float4 ----
        {
            float4* op4 = reinterpret_cast<float4*>(out_path + wrow0 * 65);
            const float4* b4 = reinterpret_cast<const float4*>(wbuf);
            #pragma unroll
            for (int k = 0; k < 17; ++k) {
                int idx = lane + k * 32;
                if (idx < 520) op4[idx] = b4[idx];
            }
        }
        __syncwarp();   // path reads done before node overwrite

        // ---- write node rows [32][76] from live registers ----
        {
            float* rn = wbuf + lane * 76;
            #pragma unroll
            for (int i = 0; i < 65; ++i) rn[i] = v[i];
            #pragma unroll
            for (int g = 0; g < 8; ++g) rn[65 + g] = pl2[g];
            rn[73] = pt0;
            rn[74] = pt1;
            rn[75] = 1.0f;
        }
        __syncwarp();

        // ---- stream node rows: 608 float4 exact ----
        {
            float4* on4 = reinterpret_cast<float4*>(out_node + wrow0 * 76);
            const float4* b4 = reinterpret_cast<const float4*>(wbuf);
            #pragma unroll
            for (int k = 0; k < 19; ++k) {
                int idx = lane + k * 32;
                on4[idx] = b4[idx];
            }
        }
        __syncwarp();   // region fully consumed before next-next prefetch reuses it

        cur ^= 1;
    }
}

extern "C" void kernel_launch(void* const* d_in, const int* in_sizes, int n_in,
                              void* d_out, int out_size)
{
    const float* x = (const float*)d_in[0];
    const long long N = (long long)in_sizes[0] / 65;   // 524288
    float* out_path = (float*)d_out;
    float* out_node = out_path + N * 65;

    const int nChunks = (int)(N / ROWS_W);             // 16384
    const int blocks = 148 * 5;                        // 5 blocks/SM (smem-capped)
    const int nWarpsTotal = blocks * WARPS;            // 1480
    molemap_kernel<<<blocks, NT>>>(x, out_path, out_node, nChunks, nWarpsTotal);
}